// round 4
// baseline (speedup 1.0000x reference)
#include <cuda_runtime.h>
#include <math.h>

#define HD 64
#define NE 1024
#define TT 4096
#define NB 4
#define BT (NB*TT)
#define BK 32          // kv cols per pipeline stage
#define BQ 32          // q rows per CTA tile
#define NTILES 128     // TT/BQ

typedef unsigned long long u64;
typedef unsigned int u32;

// Scratch for projected q,k,v — device globals (no allocs allowed)
__device__ float g_q[BT*HD];
__device__ float g_k[BT*HD];
__device__ float g_v[BT*HD];

// ---------------- packed fp32x2 helpers (Blackwell FFMA2 via PTX) ----------
__device__ __forceinline__ u64 ffma2(u64 a, u64 b, u64 c) {
    u64 d; asm("fma.rn.f32x2 %0, %1, %2, %3;" : "=l"(d) : "l"(a), "l"(b), "l"(c));
    return d;
}
__device__ __forceinline__ u64 mul2(u64 a, u64 b) {
    u64 d; asm("mul.rn.f32x2 %0, %1, %2;" : "=l"(d) : "l"(a), "l"(b));
    return d;
}
__device__ __forceinline__ u64 pack2(float x, float y) {
    union { float2 f; u64 u; } t; t.f = make_float2(x, y); return t.u;
}
__device__ __forceinline__ float2 unpack2(u64 a) {
    union { float2 f; u64 u; } t; t.u = a; return t.f;
}
union F4 { float4 f; u64 u[2]; };

__device__ __forceinline__ u32 s2u(const void* p) {
    return (u32)__cvta_generic_to_shared(p);
}
__device__ __forceinline__ void mbar_init(u32 mb, u32 cnt) {
    asm volatile("mbarrier.init.shared.b64 [%0], %1;" :: "r"(mb), "r"(cnt) : "memory");
}
__device__ __forceinline__ void mbar_expect(u32 mb, u32 tx) {
    asm volatile("mbarrier.arrive.expect_tx.shared.b64 _, [%0], %1;" :: "r"(mb), "r"(tx) : "memory");
}
__device__ __forceinline__ void bulk_g2s(u32 dst, const void* src, u32 bytes, u32 mb) {
    asm volatile("cp.async.bulk.shared::cluster.global.mbarrier::complete_tx::bytes [%0], [%1], %2, [%3];"
                 :: "r"(dst), "l"(src), "r"(bytes), "r"(mb) : "memory");
}
__device__ __forceinline__ void waitpar(u32 mb, u32 ph) {
    asm volatile(
        "{\n\t.reg .pred P;\n"
        "W%=:\n\t"
        "mbarrier.try_wait.parity.acquire.cta.shared::cta.b64 P, [%0], %1, 0x989680;\n\t"
        "@P bra D%=;\n\t"
        "bra W%=;\n"
        "D%=:\n\t}"
        :: "r"(mb), "r"(ph) : "memory");
}

// ---------------------------------------------------------------------------
// Kernel 1: fused QKV projection (unchanged from R1; ~158us, fp32x2)
// ---------------------------------------------------------------------------
__global__ __launch_bounds__(256, 2) void qkv_kernel(
    const float* __restrict__ x,
    const float* __restrict__ Wk,
    const float* __restrict__ Wq,
    const float* __restrict__ Wv)
{
    __shared__ float xs[64 * 32];
    __shared__ float ws[32 * 192];

    const int tid  = threadIdx.x;
    const int warp = tid >> 5;
    const int lane = tid & 31;
    const int row0 = blockIdx.x * 64;

    u64 acc[8][3];
    #pragma unroll
    for (int r = 0; r < 8; r++)
        #pragma unroll
        for (int j = 0; j < 3; j++) acc[r][j] = 0ull;

    for (int kk = 0; kk < NE; kk += 32) {
        __syncthreads();
        #pragma unroll
        for (int i = 0; i < 2; i++) {
            int idx = tid + i * 256;
            int r = idx >> 3, q4 = idx & 7;
            float4 v = *(const float4*)&x[(row0 + r) * NE + kk + q4 * 4];
            *(float4*)&xs[r * 32 + q4 * 4] = v;
        }
        #pragma unroll
        for (int i = 0; i < 6; i++) {
            int idx  = tid + i * 256;
            int ccol = idx % 48;
            int k    = idx / 48;
            int c0   = ccol * 4;
            const float* W = (c0 < 64) ? Wk : (c0 < 128) ? Wq : Wv;
            float4 v = *(const float4*)&W[(kk + k) * HD + (c0 & 63)];
            *(float4*)&ws[k * 192 + c0] = v;
        }
        __syncthreads();

        #pragma unroll
        for (int k = 0; k < 32; k++) {
            u64 w0 = *(const u64*)&ws[k * 192 + lane * 6];
            u64 w1 = *(const u64*)&ws[k * 192 + lane * 6 + 2];
            u64 w2 = *(const u64*)&ws[k * 192 + lane * 6 + 4];
            #pragma unroll
            for (int rr = 0; rr < 8; rr++) {
                float xv = xs[(warp * 8 + rr) * 32 + k];
                u64 xb = pack2(xv, xv);
                acc[rr][0] = ffma2(xb, w0, acc[rr][0]);
                acc[rr][1] = ffma2(xb, w1, acc[rr][1]);
                acc[rr][2] = ffma2(xb, w2, acc[rr][2]);
            }
        }
    }

    const float qscale = 0.03125f;  // 1024^-0.5 folded into q
    #pragma unroll
    for (int rr = 0; rr < 8; rr++) {
        int row = row0 + warp * 8 + rr;
        #pragma unroll
        for (int j = 0; j < 3; j++) {
            int c   = lane * 6 + j * 2;
            int mat = c >> 6;
            int h   = c & 63;
            float2 o = unpack2(acc[rr][j]);
            float* dst = (mat == 0) ? g_k : (mat == 1) ? g_q : g_v;
            if (mat == 1) { o.x *= qscale; o.y *= qscale; }
            *(float2*)&dst[row * HD + h] = o;
        }
    }
}

// ---------------------------------------------------------------------------
// Kernel 2: causal flash attention, lane-per-row, broadcast-operand fp32x2.
// CTA: 64 threads (2 warps). Tile: 32 q rows (lane r owns row r0+r fully in
// registers: Q 64 f32, O 64 f32, private m/l). Warps split kv cols (16 each),
// run independent online softmax, merge once per tile (LSE merge).
// K/V tiles double-buffered in smem via cp.async.bulk + mbarrier.
// Grid launched largest-tile-first for causal LPT balance.
// ---------------------------------------------------------------------------
#define OFF_MBAR 0
#define OFF_K    64
#define OFF_V    (OFF_K + 2*BK*HD*4)          // 64 + 16384
#define OFF_MG   (OFF_V + 2*BK*HD*4)          // 32832
#define OFF_ML   (OFF_MG + BQ*65*4)           // 41152
#define SMEM_SZ  (OFF_ML + 2*BQ*4)            // 41408

__global__ __launch_bounds__(64) void attn_kernel(float* __restrict__ out)
{
    extern __shared__ char sm[];
    const int tid  = threadIdx.x;
    const int wid  = tid >> 5;
    const int lane = tid & 31;
    const int b    = blockIdx.y;

    const int t    = NTILES - 1 - (int)blockIdx.x;   // biggest tiles first (LPT)
    const int ntot = t + 1;                           // kv stages of BK=32
    const int r0   = t * BQ;
    const int row  = r0 + lane;

    const float* __restrict__ kb = g_k + (size_t)b * TT * HD;
    const float* __restrict__ vb = g_v + (size_t)b * TT * HD;
    const float* __restrict__ qb = g_q + (size_t)b * TT * HD;
    float* __restrict__ ob = out + (size_t)b * TT * HD;

    const u32 mb0 = s2u(sm + OFF_MBAR);
    const u32 mb1 = mb0 + 8;

    if (tid == 0) { mbar_init(mb0, 1); mbar_init(mb1, 1); }
    __syncthreads();

    // prologue: kick off stages 0 and 1
    if (tid == 0) {
        mbar_expect(mb0, 2 * BK * HD * 4);
        bulk_g2s(s2u(sm + OFF_K), kb, BK * HD * 4, mb0);
        bulk_g2s(s2u(sm + OFF_V), vb, BK * HD * 4, mb0);
        if (ntot > 1) {
            mbar_expect(mb1, 2 * BK * HD * 4);
            bulk_g2s(s2u(sm + OFF_K + BK * HD * 4), kb + BK * HD, BK * HD * 4, mb1);
            bulk_g2s(s2u(sm + OFF_V + BK * HD * 4), vb + BK * HD, BK * HD * 4, mb1);
        }
    }

    // Q row into registers (64 f32 = 32 u64)
    u64 q2[32], o2[32];
    {
        const float* qr = qb + (size_t)row * HD;
        #pragma unroll
        for (int h4 = 0; h4 < 16; h4++) {
            F4 v; v.f = *(const float4*)(qr + h4 * 4);
            q2[2*h4] = v.u[0]; q2[2*h4+1] = v.u[1];
        }
    }
    #pragma unroll
    for (int i = 0; i < 32; i++) o2[i] = 0ull;
    float m = -1e30f, l = 0.f;

    const int jb = wid * 16;        // this warp's col offset within stage
    u32 ph[2] = {0, 0};

    for (int gi = 0; gi < ntot; gi++) {
        const int s  = gi & 1;
        const int j0 = gi * BK;
        waitpar(s ? mb1 : mb0, ph[s]); ph[s] ^= 1;

        const float* Kst = (const float*)(sm + OFF_K + s * BK * HD * 4);
        const float* Vst = (const float*)(sm + OFF_V + s * BK * HD * 4);

        // ---- S = q . K^T for my 16 cols (broadcast LDS.128 of K rows) ----
        float sv[16];
        #pragma unroll
        for (int g = 0; g < 2; g++) {
            u64 acc[8];
            #pragma unroll
            for (int c = 0; c < 8; c++) acc[c] = 0ull;
            const float* Kc = Kst + (jb + g * 8) * HD;
            #pragma unroll
            for (int h4 = 0; h4 < 16; h4++) {
                #pragma unroll
                for (int c = 0; c < 8; c++) {
                    F4 k4; k4.f = *(const float4*)(Kc + c * HD + h4 * 4);
                    acc[c] = ffma2(q2[2*h4],   k4.u[0], acc[c]);
                    acc[c] = ffma2(q2[2*h4+1], k4.u[1], acc[c]);
                }
            }
            #pragma unroll
            for (int c = 0; c < 8; c++) {
                float2 tt = unpack2(acc[c]);
                sv[g*8 + c] = tt.x + tt.y;
            }
        }

        // ---- causal mask + online softmax (lane-private) ----
        #pragma unroll
        for (int c = 0; c < 16; c++)
            if (j0 + jb + c > row) sv[c] = -1e30f;

        float tmax = sv[0];
        #pragma unroll
        for (int c = 1; c < 16; c++) tmax = fmaxf(tmax, sv[c]);
        float mnew  = fmaxf(m, tmax);
        float scale = __expf(m - mnew);
        float p[16], rs = 0.f;
        #pragma unroll
        for (int c = 0; c < 16; c++) { p[c] = __expf(sv[c] - mnew); rs += p[c]; }
        l = l * scale + rs;
        m = mnew;
        u64 sc2 = pack2(scale, scale);
        #pragma unroll
        for (int i = 0; i < 32; i++) o2[i] = mul2(o2[i], sc2);

        // ---- O += P V (broadcast LDS.128 of V rows) ----
        #pragma unroll
        for (int c = 0; c < 16; c++) {
            u64 p2 = pack2(p[c], p[c]);
            const float* Vc = Vst + (jb + c) * HD;
            #pragma unroll
            for (int h4 = 0; h4 < 16; h4++) {
                F4 v4; v4.f = *(const float4*)(Vc + h4 * 4);
                o2[2*h4]   = ffma2(p2, v4.u[0], o2[2*h4]);
                o2[2*h4+1] = ffma2(p2, v4.u[1], o2[2*h4+1]);
            }
        }

        __syncthreads();   // both warps done with stage s
        if (tid == 0 && gi + 2 < ntot) {
            int jn = (gi + 2) * BK;
            u32 mb = (s == 0) ? mb0 : mb1;
            u32 dk = s2u(sm + OFF_K + s * BK * HD * 4);
            u32 dv = s2u(sm + OFF_V + s * BK * HD * 4);
            mbar_expect(mb, 2 * BK * HD * 4);
            bulk_g2s(dk, kb + (size_t)jn * HD, BK * HD * 4, mb);
            bulk_g2s(dv, vb + (size_t)jn * HD, BK * HD * 4, mb);
        }
    }

    // ---- merge the two warps' partial softmax states, write O ----
    float* MG = (float*)(sm + OFF_MG);   // [32][65] padded, conflict-free
    float* ML = (float*)(sm + OFF_ML);
    if (wid == 1) {
        #pragma unroll
        for (int h4 = 0; h4 < 16; h4++) {
            float2 t0 = unpack2(o2[2*h4]);
            float2 t1 = unpack2(o2[2*h4+1]);
            MG[lane*65 + h4*4 + 0] = t0.x;
            MG[lane*65 + h4*4 + 1] = t0.y;
            MG[lane*65 + h4*4 + 2] = t1.x;
            MG[lane*65 + h4*4 + 3] = t1.y;
        }
        ML[lane]      = m;
        ML[32 + lane] = l;
    }
    __syncthreads();
    if (wid == 0) {
        float m1 = ML[lane], l1 = ML[32 + lane];
        float mf = fmaxf(m, m1);
        float a0 = __expf(m - mf), a1 = __expf(m1 - mf);
        float inv = 1.0f / (a0 * l + a1 * l1);
        a0 *= inv; a1 *= inv;
        float* orow = ob + (size_t)row * HD;
        #pragma unroll
        for (int h4 = 0; h4 < 16; h4++) {
            float2 t0 = unpack2(o2[2*h4]);
            float2 t1 = unpack2(o2[2*h4+1]);
            float4 r;
            r.x = a0 * t0.x + a1 * MG[lane*65 + h4*4 + 0];
            r.y = a0 * t0.y + a1 * MG[lane*65 + h4*4 + 1];
            r.z = a0 * t1.x + a1 * MG[lane*65 + h4*4 + 2];
            r.w = a0 * t1.y + a1 * MG[lane*65 + h4*4 + 3];
            *(float4*)(orow + h4 * 4) = r;
        }
    }
}

extern "C" void kernel_launch(void* const* d_in, const int* in_sizes, int n_in,
                              void* d_out, int out_size)
{
    const float* x  = (const float*)d_in[0];
    const float* Wk = (const float*)d_in[1];
    const float* Wq = (const float*)d_in[2];
    const float* Wv = (const float*)d_in[3];
    float* out = (float*)d_out;

    qkv_kernel<<<BT / 64, 256>>>(x, Wk, Wq, Wv);
    attn_kernel<<<dim3(NTILES, NB), 64, SMEM_SZ>>>(out);
}

// round 6
// speedup vs baseline: 2.2285x; 2.2285x over previous
#include <cuda_runtime.h>
#include <cuda_bf16.h>
#include <math.h>

#define HD 64
#define NE 1024
#define TT 4096
#define NB 4
#define BT (NB*TT)
#define BQ 32
#define BK 64

typedef unsigned long long u64;
typedef unsigned int u32;

// Scratch (device globals; no allocs allowed)
__device__ float g_q[BT*HD];
__device__ float g_k[BT*HD];
__device__ float g_v[BT*HD];
// W^T bf16 hi/lo, chunk-major + SW128-pre-swizzled: [chunk 16][n' 192][k 64]
__device__ __nv_bfloat16 g_wth[16*192*64];
__device__ __nv_bfloat16 g_wtl[16*192*64];

// ---------------- packed fp32x2 helpers ----------------
__device__ __forceinline__ u64 ffma2(u64 a, u64 b, u64 c) {
    u64 d; asm("fma.rn.f32x2 %0, %1, %2, %3;" : "=l"(d) : "l"(a), "l"(b), "l"(c));
    return d;
}
__device__ __forceinline__ u64 pack2(float x, float y) {
    union { float2 f; u64 u; } t; t.f = make_float2(x, y); return t.u;
}
__device__ __forceinline__ float2 unpack2(u64 a) {
    union { float2 f; u64 u; } t; t.u = a; return t.f;
}

// ---------------- PTX helpers ----------------
__device__ __forceinline__ u32 s2u(const void* p) {
    return (u32)__cvta_generic_to_shared(p);
}
__device__ __forceinline__ void mbar_init(u32 mb, u32 cnt) {
    asm volatile("mbarrier.init.shared.b64 [%0], %1;" :: "r"(mb), "r"(cnt) : "memory");
}
__device__ __forceinline__ void mbar_expect(u32 mb, u32 tx) {
    asm volatile("mbarrier.arrive.expect_tx.shared.b64 _, [%0], %1;" :: "r"(mb), "r"(tx) : "memory");
}
__device__ __forceinline__ void bulk_g2s(u32 dst, const void* src, u32 bytes, u32 mb) {
    asm volatile("cp.async.bulk.shared::cluster.global.mbarrier::complete_tx::bytes [%0], [%1], %2, [%3];"
                 :: "r"(dst), "l"(src), "r"(bytes), "r"(mb) : "memory");
}
__device__ __forceinline__ void waitpar(u32 mb, u32 ph) {
    asm volatile(
        "{\n\t.reg .pred P;\n"
        "W%=:\n\t"
        "mbarrier.try_wait.parity.acquire.cta.shared::cta.b64 P, [%0], %1, 0x989680;\n\t"
        "@P bra D%=;\n\t"
        "bra W%=;\n"
        "D%=:\n\t}"
        :: "r"(mb), "r"(ph) : "memory");
}
// bf16x2 pack: lower half = lo param, upper half = hi param
__device__ __forceinline__ u32 bf2(float lo, float hi) {
    u32 d; asm("cvt.rn.bf16x2.f32 %0, %1, %2;" : "=r"(d) : "f"(hi), "f"(lo));
    return d;
}
__device__ __forceinline__ void ldsm4(u32* r, u32 addr) {
    asm volatile("ldmatrix.sync.aligned.m8n8.x4.shared.b16 {%0,%1,%2,%3}, [%4];"
        : "=r"(r[0]), "=r"(r[1]), "=r"(r[2]), "=r"(r[3]) : "r"(addr));
}
__device__ __forceinline__ void ldsm2(u32* r, u32 addr) {
    asm volatile("ldmatrix.sync.aligned.m8n8.x2.shared.b16 {%0,%1}, [%2];"
        : "=r"(r[0]), "=r"(r[1]) : "r"(addr));
}
__device__ __forceinline__ void mma_bf16(float* c, const u32* a, const u32* b) {
    asm volatile("mma.sync.aligned.m16n8k16.row.col.f32.bf16.bf16.f32 "
        "{%0,%1,%2,%3}, {%4,%5,%6,%7}, {%8,%9}, {%0,%1,%2,%3};"
        : "+f"(c[0]), "+f"(c[1]), "+f"(c[2]), "+f"(c[3])
        : "r"(a[0]), "r"(a[1]), "r"(a[2]), "r"(a[3]), "r"(b[0]), "r"(b[1]));
}

// ---------------------------------------------------------------------------
// Kernel 0: W transpose + bf16 hi/lo convert + chunk-major SW128 pre-swizzle.
// ---------------------------------------------------------------------------
__global__ void wconv_kernel(const float* __restrict__ Wk,
                             const float* __restrict__ Wq,
                             const float* __restrict__ Wv)
{
    int np  = blockIdx.x;            // n' 0..191
    int mat = np >> 6;
    int n   = np & 63;
    const float* W = (mat == 0) ? Wk : (mat == 1) ? Wq : Wv;
    char* dh = (char*)g_wth;
    char* dl = (char*)g_wtl;
    for (int k = threadIdx.x; k < NE; k += blockDim.x) {
        float v = W[k * HD + n];
        __nv_bfloat16 h = __float2bfloat16(v);
        float hf = __bfloat162float(h);
        __nv_bfloat16 l = __float2bfloat16(v - hf);
        int ch = k >> 6, kc = k & 63;
        u32 off = (u32)np * 128 + kc * 2;
        u32 sw  = off ^ ((np & 7) * 16);
        *(__nv_bfloat16*)(dh + ch * 24576 + sw) = h;
        *(__nv_bfloat16*)(dl + ch * 24576 + sw) = l;
    }
}

// ---------------------------------------------------------------------------
// Kernel 1: QKV projection via mma.sync bf16 hi/lo (3 HMMA per tile term).
// CTA: 128 rows x 192 cols, 256 threads, 8 warps (4M x 2N), warp 32x96.
// W streamed by cp.async.bulk (double buffer); x LDG->cvt->STS pipelined.
// ---------------------------------------------------------------------------
#define NCH 16
#define OFF_XH 128
#define OFF_XL (128 + 16384)
#define OFF_W  (128 + 32768)
#define WSTRIDE 49152
#define P_SMEM (OFF_W + 2*WSTRIDE)

__device__ __forceinline__ u32 abyte(int row, int q) {
    return (u32)(row * 128 + (((q) ^ (row & 7)) << 4));
}

__global__ __launch_bounds__(256, 1) void proj_kernel(const float* __restrict__ x)
{
    extern __shared__ char sm[];
    const u32 smb = s2u(sm);
    const int tid  = threadIdx.x;
    const int warp = tid >> 5;
    const int lane = tid & 31;
    const int wm   = warp >> 1;       // 0..3 : row group
    const int wn   = warp & 1;        // 0..1 : col group
    const int row0 = blockIdx.x * 128;

    const u32 mb0 = smb;              // 2 mbarriers in first 16 bytes
    const u32 mb1 = smb + 8;

    if (tid == 0) { mbar_init(mb0, 1); mbar_init(mb1, 1); }
    __syncthreads();

    const char* wh_g = (const char*)g_wth;
    const char* wl_g = (const char*)g_wtl;

    if (tid == 0) {
        mbar_expect(mb0, 49152);
        bulk_g2s(smb + OFF_W,         wh_g,         24576, mb0);
        bulk_g2s(smb + OFF_W + 24576, wl_g,         24576, mb0);
        mbar_expect(mb1, 49152);
        bulk_g2s(smb + OFF_W + WSTRIDE,         wh_g + 24576, 24576, mb1);
        bulk_g2s(smb + OFF_W + WSTRIDE + 24576, wl_g + 24576, 24576, mb1);
    }

    float C[2][12][4];
    #pragma unroll
    for (int mt = 0; mt < 2; mt++)
        #pragma unroll
        for (int nt = 0; nt < 12; nt++)
            #pragma unroll
            for (int i = 0; i < 4; i++) C[mt][nt][i] = 0.f;

    // stage x chunk 0
    float4 xr[8];
    #pragma unroll
    for (int i = 0; i < 8; i++) {
        int idx = tid + i * 256;            // 0..2047
        int r = idx >> 4, c4 = idx & 15;
        xr[i] = *(const float4*)&x[(size_t)(row0 + r) * NE + c4 * 4];
    }
    #pragma unroll
    for (int i = 0; i < 8; i++) {
        int idx = tid + i * 256;
        int r = idx >> 4, c4 = idx & 15;
        float4 v = xr[i];
        u32 h01 = bf2(v.x, v.y);
        u32 h23 = bf2(v.z, v.w);
        float lx = v.x - __uint_as_float(h01 << 16);
        float ly = v.y - __uint_as_float(h01 & 0xFFFF0000u);
        float lz = v.z - __uint_as_float(h23 << 16);
        float lw = v.w - __uint_as_float(h23 & 0xFFFF0000u);
        u32 l01 = bf2(lx, ly);
        u32 l23 = bf2(lz, lw);
        u32 off = (u32)r * 128 + c4 * 8;
        u32 sw  = off ^ ((r & 7) * 16);
        *(u64*)(sm + OFF_XH + sw) = (u64)h01 | ((u64)h23 << 32);
        *(u64*)(sm + OFF_XL + sw) = (u64)l01 | ((u64)l23 << 32);
    }
    __syncthreads();

    u32 ph[2] = {0, 0};

    // per-lane ldmatrix geometry
    const int rowA0 = wm * 32 + (lane & 15);        // mt adds +16
    const int qselA = lane >> 4;
    const int nrow0 = wn * 96 + (lane & 7);         // nt adds +8
    const int gB    = (lane >> 3) & 1;

    for (int c = 0; c < NCH; c++) {
        // prefetch x chunk c+1 into regs
        if (c < NCH - 1) {
            const int kk = (c + 1) * 64;
            #pragma unroll
            for (int i = 0; i < 8; i++) {
                int idx = tid + i * 256;
                int r = idx >> 4, c4 = idx & 15;
                xr[i] = *(const float4*)&x[(size_t)(row0 + r) * NE + kk + c4 * 4];
            }
        }

        waitpar((c & 1) ? mb1 : mb0, ph[c & 1]);
        ph[c & 1] ^= 1;

        const u32 wbase = smb + OFF_W + (c & 1) * WSTRIDE;

        #pragma unroll
        for (int ks = 0; ks < 4; ks++) {
            u32 ah[2][4], al[2][4];
            #pragma unroll
            for (int mt = 0; mt < 2; mt++) {
                u32 ba = abyte(rowA0 + mt * 16, ks * 2 + qselA);
                ldsm4(ah[mt], smb + OFF_XH + ba);
                ldsm4(al[mt], smb + OFF_XL + ba);
            }
            #pragma unroll
            for (int nt = 0; nt < 12; nt++) {
                u32 bh[2], bl[2];
                u32 bb = abyte(nrow0 + nt * 8, ks * 2 + gB);
                ldsm2(bh, wbase + bb);
                ldsm2(bl, wbase + 24576 + bb);
                #pragma unroll
                for (int mt = 0; mt < 2; mt++) {
                    mma_bf16(C[mt][nt], ah[mt], bh);
                    mma_bf16(C[mt][nt], ah[mt], bl);
                    mma_bf16(C[mt][nt], al[mt], bh);
                }
            }
        }
        __syncthreads();

        if (c < NCH - 1) {
            // store staged x chunk c+1
            #pragma unroll
            for (int i = 0; i < 8; i++) {
                int idx = tid + i * 256;
                int r = idx >> 4, c4 = idx & 15;
                float4 v = xr[i];
                u32 h01 = bf2(v.x, v.y);
                u32 h23 = bf2(v.z, v.w);
                float lx = v.x - __uint_as_float(h01 << 16);
                float ly = v.y - __uint_as_float(h01 & 0xFFFF0000u);
                float lz = v.z - __uint_as_float(h23 << 16);
                float lw = v.w - __uint_as_float(h23 & 0xFFFF0000u);
                u32 l01 = bf2(lx, ly);
                u32 l23 = bf2(lz, lw);
                u32 off = (u32)r * 128 + c4 * 8;
                u32 sw  = off ^ ((r & 7) * 16);
                *(u64*)(sm + OFF_XH + sw) = (u64)h01 | ((u64)h23 << 32);
                *(u64*)(sm + OFF_XL + sw) = (u64)l01 | ((u64)l23 << 32);
            }
            // kick W bulk for chunk c+2 into the buffer just freed
            if (tid == 0 && c + 2 < NCH) {
                u32 mb = (c & 1) ? mb1 : mb0;
                u32 dst = smb + OFF_W + (c & 1) * WSTRIDE;
                mbar_expect(mb, 49152);
                bulk_g2s(dst,         wh_g + (size_t)(c + 2) * 24576, 24576, mb);
                bulk_g2s(dst + 24576, wl_g + (size_t)(c + 2) * 24576, 24576, mb);
            }
        }
        __syncthreads();
    }

    // epilogue: C -> g_k/g_q/g_v (fp32), fold 1024^-0.5 into q
    #pragma unroll
    for (int mt = 0; mt < 2; mt++) {
        int r_lo = row0 + wm * 32 + mt * 16 + (lane >> 2);
        #pragma unroll
        for (int nt = 0; nt < 12; nt++) {
            int col = wn * 96 + nt * 8 + 2 * (lane & 3);
            int mat = col >> 6;
            int h   = col & 63;
            float* dst = (mat == 0) ? g_k : (mat == 1) ? g_q : g_v;
            float sc = (mat == 1) ? 0.03125f : 1.0f;
            float2 v0 = make_float2(C[mt][nt][0] * sc, C[mt][nt][1] * sc);
            float2 v1 = make_float2(C[mt][nt][2] * sc, C[mt][nt][3] * sc);
            *(float2*)&dst[(size_t)r_lo * HD + h]       = v0;
            *(float2*)&dst[(size_t)(r_lo + 8) * HD + h] = v1;
        }
    }
}

// ---------------------------------------------------------------------------
// Kernel 2: causal flash attention (R1 version, known-good 395us).
// ---------------------------------------------------------------------------
__global__ __launch_bounds__(256, 2) void attn_kernel(float* __restrict__ out)
{
    __shared__ float Qs[BQ * HD];
    __shared__ float Ks[BK * HD];
    __shared__ float Vs[BK * HD];
    __shared__ float Ps[BQ * HD];

    const int tid  = threadIdx.x;
    const int warp = tid >> 5;
    const int lane = tid & 31;
    const int b    = blockIdx.y;
    const int base = b * TT * HD;
    const int pidx = blockIdx.x;

    for (int ti = 0; ti < 2; ti++) {
        const int t      = (ti == 0) ? pidx : (127 - pidx);
        const int n_iter = t / 2 + 1;
        const int r0     = t * BQ;

        __syncthreads();
        #pragma unroll
        for (int i = 0; i < 4; i++) {
            int idx = tid + i * 256;
            int r = idx >> 5, pp = idx & 31;
            float2 v = *(const float2*)&g_q[base + (r0 + r) * HD + pp * 2];
            *(float2*)&Qs[r * HD + 2 * (pp ^ (r & 31))] = v;
        }

        u64 o2[4] = {0ull, 0ull, 0ull, 0ull};
        float m[4], l[4];
        #pragma unroll
        for (int rr = 0; rr < 4; rr++) { m[rr] = -INFINITY; l[rr] = 0.f; }

        const int c0 = lane, c1 = lane + 32;

        for (int it = 0; it < n_iter; it++) {
            const int j0 = it * BK;
            #pragma unroll
            for (int i = 0; i < 8; i++) {
                int idx = tid + i * 256;
                int r = idx >> 5, pp = idx & 31;
                float2 kv = *(const float2*)&g_k[base + (j0 + r) * HD + pp * 2];
                *(float2*)&Ks[r * HD + 2 * (pp ^ (r & 31))] = kv;
                float2 vv = *(const float2*)&g_v[base + (j0 + r) * HD + pp * 2];
                *(float2*)&Vs[r * HD + pp * 2] = vv;
            }
            __syncthreads();

            u64 s2[4][2] = {};
            #pragma unroll
            for (int pp = 0; pp < 32; pp++) {
                u64 k2a = *(const u64*)&Ks[c0 * HD + 2 * (pp ^ lane)];
                u64 k2b = *(const u64*)&Ks[c1 * HD + 2 * (pp ^ lane)];
                #pragma unroll
                for (int rr = 0; rr < 4; rr++) {
                    int r = warp * 4 + rr;
                    u64 q2 = *(const u64*)&Qs[r * HD + 2 * (pp ^ (r & 31))];
                    s2[rr][0] = ffma2(q2, k2a, s2[rr][0]);
                    s2[rr][1] = ffma2(q2, k2b, s2[rr][1]);
                }
            }

            const bool maskit = (it == n_iter - 1);
            #pragma unroll
            for (int rr = 0; rr < 4; rr++) {
                const int grow = r0 + warp * 4 + rr;
                float2 a  = unpack2(s2[rr][0]);
                float2 bb = unpack2(s2[rr][1]);
                float sA = a.x + a.y;
                float sB = bb.x + bb.y;
                if (maskit) {
                    if (j0 + c0 > grow) sA = -INFINITY;
                    if (j0 + c1 > grow) sB = -INFINITY;
                }
                float tmax = fmaxf(sA, sB);
                #pragma unroll
                for (int off = 16; off > 0; off >>= 1)
                    tmax = fmaxf(tmax, __shfl_xor_sync(0xffffffffu, tmax, off));
                float mnew = fmaxf(m[rr], tmax);
                float pA = __expf(sA - mnew);
                float pB = __expf(sB - mnew);
                float rsum = pA + pB;
                #pragma unroll
                for (int off = 16; off > 0; off >>= 1)
                    rsum += __shfl_xor_sync(0xffffffffu, rsum, off);
                float scale = __expf(m[rr] - mnew);
                l[rr] = l[rr] * scale + rsum;
                m[rr] = mnew;
                o2[rr] = ffma2(o2[rr], pack2(scale, scale), 0ull);
                Ps[(warp * 4 + rr) * HD + c0] = pA;
                Ps[(warp * 4 + rr) * HD + c1] = pB;
            }
            __syncthreads();

            #pragma unroll
            for (int cc = 0; cc < 32; cc++) {
                int c = cc * 2;
                u64 v2a = *(const u64*)&Vs[c * HD + lane * 2];
                u64 v2b = *(const u64*)&Vs[(c + 1) * HD + lane * 2];
                #pragma unroll
                for (int rr = 0; rr < 4; rr++) {
                    float2 p2 = *(const float2*)&Ps[(warp * 4 + rr) * HD + c];
                    o2[rr] = ffma2(pack2(p2.x, p2.x), v2a, o2[rr]);
                    o2[rr] = ffma2(pack2(p2.y, p2.y), v2b, o2[rr]);
                }
            }
            __syncthreads();
        }

        #pragma unroll
        for (int rr = 0; rr < 4; rr++) {
            float inv = 1.0f / l[rr];
            float2 o = unpack2(o2[rr]);
            o.x *= inv; o.y *= inv;
            int grow = r0 + warp * 4 + rr;
            *(float2*)&out[base + grow * HD + lane * 2] = o;
        }
    }
}

extern "C" void kernel_launch(void* const* d_in, const int* in_sizes, int n_in,
                              void* d_out, int out_size)
{
    const float* x  = (const float*)d_in[0];
    const float* Wk = (const float*)d_in[1];
    const float* Wq = (const float*)d_in[2];
    const float* Wv = (const float*)d_in[3];
    float* out = (float*)d_out;

    cudaFuncSetAttribute(proj_kernel, cudaFuncAttributeMaxDynamicSharedMemorySize, P_SMEM);

    wconv_kernel<<<192, 256>>>(Wk, Wq, Wv);
    proj_kernel<<<BT / 128, 256, P_SMEM>>>(x);
    attn_kernel<<<dim3(64, NB), 256>>>(out);
}

// round 7
// speedup vs baseline: 6.9348x; 3.1119x over previous
#include <cuda_runtime.h>
#include <cuda_bf16.h>
#include <math.h>

#define HD 64
#define NE 1024
#define TT 4096
#define NB 4
#define BT (NB*TT)

typedef unsigned long long u64;
typedef unsigned int u32;

// ---- device scratch (no allocs allowed) ----
// W^T bf16 hi/lo, chunk-major + SW128-pre-swizzled: [chunk 16][n' 192][k 64]
__device__ __align__(128) __nv_bfloat16 g_wth[16*192*64];
__device__ __align__(128) __nv_bfloat16 g_wtl[16*192*64];
// q/k blocked: [tile 256][s 64][h 64] bf16, swizzled; v transposed: [tile][h 64][s 64]
__device__ __align__(128) __nv_bfloat16 g_qh[BT*HD];
__device__ __align__(128) __nv_bfloat16 g_ql[BT*HD];
__device__ __align__(128) __nv_bfloat16 g_kh[BT*HD];
__device__ __align__(128) __nv_bfloat16 g_kl[BT*HD];
__device__ __align__(128) __nv_bfloat16 g_vth[BT*HD];
__device__ __align__(128) __nv_bfloat16 g_vtl[BT*HD];

// ---------------- PTX helpers ----------------
__device__ __forceinline__ u32 s2u(const void* p) {
    return (u32)__cvta_generic_to_shared(p);
}
__device__ __forceinline__ void mbar_init(u32 mb, u32 cnt) {
    asm volatile("mbarrier.init.shared.b64 [%0], %1;" :: "r"(mb), "r"(cnt) : "memory");
}
__device__ __forceinline__ void mbar_expect(u32 mb, u32 tx) {
    asm volatile("mbarrier.arrive.expect_tx.shared.b64 _, [%0], %1;" :: "r"(mb), "r"(tx) : "memory");
}
__device__ __forceinline__ void bulk_g2s(u32 dst, const void* src, u32 bytes, u32 mb) {
    asm volatile("cp.async.bulk.shared::cluster.global.mbarrier::complete_tx::bytes [%0], [%1], %2, [%3];"
                 :: "r"(dst), "l"(src), "r"(bytes), "r"(mb) : "memory");
}
__device__ __forceinline__ void waitpar(u32 mb, u32 ph) {
    asm volatile(
        "{\n\t.reg .pred P;\n"
        "W%=:\n\t"
        "mbarrier.try_wait.parity.acquire.cta.shared::cta.b64 P, [%0], %1, 0x989680;\n\t"
        "@P bra D%=;\n\t"
        "bra W%=;\n"
        "D%=:\n\t}"
        :: "r"(mb), "r"(ph) : "memory");
}
// bf16x2 pack: low half = lo param, high half = hi param
__device__ __forceinline__ u32 bf2(float lo, float hi) {
    u32 d; asm("cvt.rn.bf16x2.f32 %0, %1, %2;" : "=r"(d) : "f"(hi), "f"(lo));
    return d;
}
__device__ __forceinline__ float lo16f(u32 h) { return __uint_as_float(h << 16); }
__device__ __forceinline__ float hi16f(u32 h) { return __uint_as_float(h & 0xFFFF0000u); }
__device__ __forceinline__ void ldsm4(u32* r, u32 addr) {
    asm volatile("ldmatrix.sync.aligned.m8n8.x4.shared.b16 {%0,%1,%2,%3}, [%4];"
        : "=r"(r[0]), "=r"(r[1]), "=r"(r[2]), "=r"(r[3]) : "r"(addr));
}
__device__ __forceinline__ void ldsm2(u32* r, u32 addr) {
    asm volatile("ldmatrix.sync.aligned.m8n8.x2.shared.b16 {%0,%1}, [%2];"
        : "=r"(r[0]), "=r"(r[1]) : "r"(addr));
}
__device__ __forceinline__ void mma_bf16(float* c, const u32* a, const u32* b) {
    asm volatile("mma.sync.aligned.m16n8k16.row.col.f32.bf16.bf16.f32 "
        "{%0,%1,%2,%3}, {%4,%5,%6,%7}, {%8,%9}, {%0,%1,%2,%3};"
        : "+f"(c[0]), "+f"(c[1]), "+f"(c[2]), "+f"(c[3])
        : "r"(a[0]), "r"(a[1]), "r"(a[2]), "r"(a[3]), "r"(b[0]), "r"(b[1]));
}

// ---------------------------------------------------------------------------
// Kernel 0: W transpose + bf16 hi/lo + chunk-major SW128 pre-swizzle.
// ---------------------------------------------------------------------------
__global__ void wconv_kernel(const float* __restrict__ Wk,
                             const float* __restrict__ Wq,
                             const float* __restrict__ Wv)
{
    int np  = blockIdx.x;            // 0..191
    int mat = np >> 6;
    int n   = np & 63;
    const float* W = (mat == 0) ? Wk : (mat == 1) ? Wq : Wv;
    char* dh = (char*)g_wth;
    char* dl = (char*)g_wtl;
    for (int k = threadIdx.x; k < NE; k += blockDim.x) {
        float v = W[k * HD + n];
        __nv_bfloat16 h = __float2bfloat16(v);
        float hf = __bfloat162float(h);
        __nv_bfloat16 l = __float2bfloat16(v - hf);
        int ch = k >> 6, kc = k & 63;
        u32 off = (u32)np * 128 + kc * 2;
        u32 sw  = off ^ ((np & 7) * 16);
        *(__nv_bfloat16*)(dh + ch * 24576 + sw) = h;
        *(__nv_bfloat16*)(dl + ch * 24576 + sw) = l;
    }
}

// ---------------------------------------------------------------------------
// Kernel 1: QKV projection via mma.sync bf16 hi/lo. Epilogue writes q/k/v as
// bf16 hi/lo in blocked+swizzled tile layouts (v transposed) for attention.
// ---------------------------------------------------------------------------
#define NCH 16
#define OFF_XH 128
#define OFF_XL (128 + 16384)
#define OFF_W  (128 + 32768)
#define WSTRIDE 49152
#define P_SMEM (OFF_W + 2*WSTRIDE)

__device__ __forceinline__ u32 abyte(int row, int q) {
    return (u32)(row * 128 + (((q) ^ (row & 7)) << 4));
}

__global__ __launch_bounds__(256, 1) void proj_kernel(const float* __restrict__ x)
{
    extern __shared__ char sm[];
    const u32 smb = s2u(sm);
    const int tid  = threadIdx.x;
    const int warp = tid >> 5;
    const int lane = tid & 31;
    const int wm   = warp >> 1;
    const int wn   = warp & 1;
    const int row0 = blockIdx.x * 128;

    const u32 mb0 = smb;
    const u32 mb1 = smb + 8;

    if (tid == 0) { mbar_init(mb0, 1); mbar_init(mb1, 1); }
    __syncthreads();

    const char* wh_g = (const char*)g_wth;
    const char* wl_g = (const char*)g_wtl;

    if (tid == 0) {
        mbar_expect(mb0, 49152);
        bulk_g2s(smb + OFF_W,         wh_g, 24576, mb0);
        bulk_g2s(smb + OFF_W + 24576, wl_g, 24576, mb0);
        mbar_expect(mb1, 49152);
        bulk_g2s(smb + OFF_W + WSTRIDE,         wh_g + 24576, 24576, mb1);
        bulk_g2s(smb + OFF_W + WSTRIDE + 24576, wl_g + 24576, 24576, mb1);
    }

    float C[2][12][4];
    #pragma unroll
    for (int mt = 0; mt < 2; mt++)
        #pragma unroll
        for (int nt = 0; nt < 12; nt++)
            #pragma unroll
            for (int i = 0; i < 4; i++) C[mt][nt][i] = 0.f;

    float4 xr[8];
    #pragma unroll
    for (int i = 0; i < 8; i++) {
        int idx = tid + i * 256;
        int r = idx >> 4, c4 = idx & 15;
        xr[i] = *(const float4*)&x[(size_t)(row0 + r) * NE + c4 * 4];
    }
    #pragma unroll
    for (int i = 0; i < 8; i++) {
        int idx = tid + i * 256;
        int r = idx >> 4, c4 = idx & 15;
        float4 v = xr[i];
        u32 h01 = bf2(v.x, v.y);
        u32 h23 = bf2(v.z, v.w);
        u32 l01 = bf2(v.x - lo16f(h01), v.y - hi16f(h01));
        u32 l23 = bf2(v.z - lo16f(h23), v.w - hi16f(h23));
        u32 off = (u32)r * 128 + c4 * 8;
        u32 sw  = off ^ ((r & 7) * 16);
        *(u64*)(sm + OFF_XH + sw) = (u64)h01 | ((u64)h23 << 32);
        *(u64*)(sm + OFF_XL + sw) = (u64)l01 | ((u64)l23 << 32);
    }
    __syncthreads();

    u32 ph[2] = {0, 0};
    const int rowA0 = wm * 32 + (lane & 15);
    const int qselA = lane >> 4;
    const int nrow0 = wn * 96 + (lane & 7);
    const int gB    = (lane >> 3) & 1;

    for (int c = 0; c < NCH; c++) {
        if (c < NCH - 1) {
            const int kk = (c + 1) * 64;
            #pragma unroll
            for (int i = 0; i < 8; i++) {
                int idx = tid + i * 256;
                int r = idx >> 4, c4 = idx & 15;
                xr[i] = *(const float4*)&x[(size_t)(row0 + r) * NE + kk + c4 * 4];
            }
        }

        waitpar((c & 1) ? mb1 : mb0, ph[c & 1]);
        ph[c & 1] ^= 1;

        const u32 wbase = smb + OFF_W + (c & 1) * WSTRIDE;

        #pragma unroll
        for (int ks = 0; ks < 4; ks++) {
            u32 ah[2][4], al[2][4];
            #pragma unroll
            for (int mt = 0; mt < 2; mt++) {
                u32 ba = abyte(rowA0 + mt * 16, ks * 2 + qselA);
                ldsm4(ah[mt], smb + OFF_XH + ba);
                ldsm4(al[mt], smb + OFF_XL + ba);
            }
            #pragma unroll
            for (int nt = 0; nt < 12; nt++) {
                u32 bh[2], bl[2];
                u32 bb = abyte(nrow0 + nt * 8, ks * 2 + gB);
                ldsm2(bh, wbase + bb);
                ldsm2(bl, wbase + 24576 + bb);
                #pragma unroll
                for (int mt = 0; mt < 2; mt++) {
                    mma_bf16(C[mt][nt], ah[mt], bh);
                    mma_bf16(C[mt][nt], ah[mt], bl);
                    mma_bf16(C[mt][nt], al[mt], bh);
                }
            }
        }
        __syncthreads();

        if (c < NCH - 1) {
            #pragma unroll
            for (int i = 0; i < 8; i++) {
                int idx = tid + i * 256;
                int r = idx >> 4, c4 = idx & 15;
                float4 v = xr[i];
                u32 h01 = bf2(v.x, v.y);
                u32 h23 = bf2(v.z, v.w);
                u32 l01 = bf2(v.x - lo16f(h01), v.y - hi16f(h01));
                u32 l23 = bf2(v.z - lo16f(h23), v.w - hi16f(h23));
                u32 off = (u32)r * 128 + c4 * 8;
                u32 sw  = off ^ ((r & 7) * 16);
                *(u64*)(sm + OFF_XH + sw) = (u64)h01 | ((u64)h23 << 32);
                *(u64*)(sm + OFF_XL + sw) = (u64)l01 | ((u64)l23 << 32);
            }
            if (tid == 0 && c + 2 < NCH) {
                u32 mb = (c & 1) ? mb1 : mb0;
                u32 dst = smb + OFF_W + (c & 1) * WSTRIDE;
                mbar_expect(mb, 49152);
                bulk_g2s(dst,         wh_g + (size_t)(c + 2) * 24576, 24576, mb);
                bulk_g2s(dst + 24576, wl_g + (size_t)(c + 2) * 24576, 24576, mb);
            }
        }
        __syncthreads();
    }

    // ---- epilogue: write q/k (blocked [tile][s][h]) and v^T ([tile][h][s]) ----
    #pragma unroll
    for (int mt = 0; mt < 2; mt++) {
        int r_lo = row0 + wm * 32 + mt * 16 + (lane >> 2);   // and r_lo+8, same tile
        size_t tb = (size_t)(r_lo >> 6) * 8192;
        int s0 = r_lo & 63, s1 = s0 + 8;
        #pragma unroll
        for (int nt = 0; nt < 12; nt++) {
            int col = wn * 96 + nt * 8 + 2 * (lane & 3);
            int mat = col >> 6;
            int h   = col & 63;
            float sc = (mat == 1) ? 0.03125f : 1.0f;   // 1024^-0.5 folded into q
            float v0 = C[mt][nt][0] * sc, v1 = C[mt][nt][1] * sc;
            float v2 = C[mt][nt][2] * sc, v3 = C[mt][nt][3] * sc;
            if (mat != 2) {
                char* dh = (mat == 0) ? (char*)g_kh : (char*)g_qh;
                char* dl = (mat == 0) ? (char*)g_kl : (char*)g_ql;
                u32 h01 = bf2(v0, v1);
                u32 l01 = bf2(v0 - lo16f(h01), v1 - hi16f(h01));
                u32 h23 = bf2(v2, v3);
                u32 l23 = bf2(v2 - lo16f(h23), v3 - hi16f(h23));
                size_t a0 = tb + s0 * 128 + ((((h >> 3) ^ (s0 & 7)) << 4) + (h & 7) * 2);
                size_t a1 = tb + s1 * 128 + ((((h >> 3) ^ (s1 & 7)) << 4) + (h & 7) * 2);
                *(u32*)(dh + a0) = h01;  *(u32*)(dl + a0) = l01;
                *(u32*)(dh + a1) = h23;  *(u32*)(dl + a1) = l23;
            } else {
                char* dh = (char*)g_vth;
                char* dl = (char*)g_vtl;
                float vv[4] = {v0, v1, v2, v3};
                #pragma unroll
                for (int e = 0; e < 4; e++) {
                    int hh = h + (e & 1);
                    int ss = (e < 2) ? s0 : s1;
                    __nv_bfloat16 bh = __float2bfloat16(vv[e]);
                    __nv_bfloat16 bl = __float2bfloat16(vv[e] - __bfloat162float(bh));
                    size_t a = tb + hh * 128 + ((((ss >> 3) ^ (hh & 7)) << 4) + (ss & 7) * 2);
                    *(__nv_bfloat16*)(dh + a) = bh;
                    *(__nv_bfloat16*)(dl + a) = bl;
                }
            }
        }
    }
}

// ---------------------------------------------------------------------------
// Kernel 2: causal flash attention via mma.sync bf16 hi/lo.
// CTA = 128 threads (4 warps), q-tile M=64 (warp owns 16 rows), BK=64 stages
// double-buffered via cp.async.bulk. CTA processes tile pair (tq, 63-tq):
// uniform 65 stages. S C-frags reused in-register as PV A-frags.
// ---------------------------------------------------------------------------
#define A_QH  128
#define A_QL  (128 + 8192)
#define A_ST  (128 + 16384)
#define A_STG 32768
#define A_SMEM (A_ST + 2*A_STG)      // 82048

__global__ __launch_bounds__(128, 1) void attn2_kernel(float* __restrict__ out)
{
    extern __shared__ char sm[];
    const u32 smb = s2u(sm);
    const int tid  = threadIdx.x;
    const int warp = tid >> 5;
    const int lane = tid & 31;
    const int b    = blockIdx.y;
    const int pidx = blockIdx.x;      // 0..31

    const u32 mb0 = smb, mb1 = smb + 8;
    if (tid == 0) { mbar_init(mb0, 1); mbar_init(mb1, 1); }
    __syncthreads();

    u32 ph[2] = {0, 0};

    // ldmatrix geometry
    const int lrowA = warp * 16 + (lane & 15);      // A-frag (Q) row
    const int lqA   = lane >> 4;                     // A-frag 16B-unit select
    const int browB = ((lane >> 4) << 3) + (lane & 7); // B-frag row-in-16
    const int bgB   = (lane >> 3) & 1;

    const char* qh_g  = (const char*)g_qh;
    const char* ql_g  = (const char*)g_ql;
    const char* kh_g  = (const char*)g_kh;
    const char* kl_g  = (const char*)g_kl;
    const char* vth_g = (const char*)g_vth;
    const char* vtl_g = (const char*)g_vtl;

    for (int ti = 0; ti < 2; ti++) {
        const int tq     = ti ? (63 - pidx) : pidx;
        const int n_iter = tq + 1;
        const size_t tgq = (size_t)(b * 64 + tq) * 8192;

        __syncthreads();   // previous tile's buffer consumers done
        if (tid == 0) {
            const size_t t0 = (size_t)(b * 64) * 8192;
            mbar_expect(mb0, 16384 + A_STG);
            bulk_g2s(smb + A_QH, qh_g + tgq, 8192, mb0);
            bulk_g2s(smb + A_QL, ql_g + tgq, 8192, mb0);
            u32 d = smb + A_ST;
            bulk_g2s(d,         kh_g  + t0, 8192, mb0);
            bulk_g2s(d + 8192,  kl_g  + t0, 8192, mb0);
            bulk_g2s(d + 16384, vth_g + t0, 8192, mb0);
            bulk_g2s(d + 24576, vtl_g + t0, 8192, mb0);
            if (n_iter > 1) {
                const size_t t1 = t0 + 8192;
                u32 d1 = d + A_STG;
                mbar_expect(mb1, A_STG);
                bulk_g2s(d1,         kh_g  + t1, 8192, mb1);
                bulk_g2s(d1 + 8192,  kl_g  + t1, 8192, mb1);
                bulk_g2s(d1 + 16384, vth_g + t1, 8192, mb1);
                bulk_g2s(d1 + 24576, vtl_g + t1, 8192, mb1);
            }
        }
        waitpar(mb0, ph[0]); ph[0] ^= 1;

        // Q frags (persistent in registers)
        u32 qfh[4][4], qfl[4][4];
        #pragma unroll
        for (int ks = 0; ks < 4; ks++) {
            u32 off = abyte(lrowA, ks * 2 + lqA);
            ldsm4(qfh[ks], smb + A_QH + off);
            ldsm4(qfl[ks], smb + A_QL + off);
        }

        float o[8][4];
        #pragma unroll
        for (int nt = 0; nt < 8; nt++)
            #pragma unroll
            for (int i = 0; i < 4; i++) o[nt][i] = 0.f;
        float m0 = -1e30f, m1 = -1e30f, l0 = 0.f, l1 = 0.f;

        for (int gi = 0; gi < n_iter; gi++) {
            const int s = gi & 1;
            if (gi > 0) { waitpar(s ? mb1 : mb0, ph[s]); ph[s] ^= 1; }
            const u32 kb = smb + A_ST + s * A_STG;
            const u32 vb = kb + 16384;

            // ---- S = Q K^T ----
            float sacc[8][4];
            #pragma unroll
            for (int nt = 0; nt < 8; nt++)
                #pragma unroll
                for (int i = 0; i < 4; i++) sacc[nt][i] = 0.f;

            #pragma unroll
            for (int ks = 0; ks < 4; ks++) {
                #pragma unroll
                for (int ntp = 0; ntp < 4; ntp++) {
                    int nr = ntp * 16 + browB;
                    u32 off = (u32)(nr * 128 + (((ks * 2 + bgB) ^ (nr & 7)) << 4));
                    u32 kh4[4], kl4[4];
                    ldsm4(kh4, kb + off);
                    ldsm4(kl4, kb + 8192 + off);
                    mma_bf16(sacc[2*ntp],   qfh[ks], kh4);
                    mma_bf16(sacc[2*ntp],   qfh[ks], kl4);
                    mma_bf16(sacc[2*ntp],   qfl[ks], kh4);
                    mma_bf16(sacc[2*ntp+1], qfh[ks], kh4 + 2);
                    mma_bf16(sacc[2*ntp+1], qfh[ks], kl4 + 2);
                    mma_bf16(sacc[2*ntp+1], qfl[ks], kh4 + 2);
                }
            }

            // ---- causal mask (diagonal stage only) ----
            if (gi == tq) {
                int rl = warp * 16 + (lane >> 2);
                #pragma unroll
                for (int nt = 0; nt < 8; nt++) {
                    int cl = nt * 8 + 2 * (lane & 3);
                    if (cl     > rl)     sacc[nt][0] = -1e30f;
                    if (cl + 1 > rl)     sacc[nt][1] = -1e30f;
                    if (cl     > rl + 8) sacc[nt][2] = -1e30f;
                    if (cl + 1 > rl + 8) sacc[nt][3] = -1e30f;
                }
            }

            // ---- online softmax (rows: lane>>2 and +8; 4 lanes share a row) ----
            float mx0 = sacc[0][0], mx1 = sacc[0][2];
            #pragma unroll
            for (int nt = 0; nt < 8; nt++) {
                mx0 = fmaxf(mx0, fmaxf(sacc[nt][0], sacc[nt][1]));
                mx1 = fmaxf(mx1, fmaxf(sacc[nt][2], sacc[nt][3]));
            }
            mx0 = fmaxf(mx0, __shfl_xor_sync(0xffffffffu, mx0, 1));
            mx0 = fmaxf(mx0, __shfl_xor_sync(0xffffffffu, mx0, 2));
            mx1 = fmaxf(mx1, __shfl_xor_sync(0xffffffffu, mx1, 1));
            mx1 = fmaxf(mx1, __shfl_xor_sync(0xffffffffu, mx1, 2));
            float mn0 = fmaxf(m0, mx0), mn1 = fmaxf(m1, mx1);
            float sc0 = __expf(m0 - mn0), sc1 = __expf(m1 - mn1);
            float sum0 = 0.f, sum1 = 0.f;
            #pragma unroll
            for (int nt = 0; nt < 8; nt++) {
                sacc[nt][0] = __expf(sacc[nt][0] - mn0);
                sacc[nt][1] = __expf(sacc[nt][1] - mn0);
                sacc[nt][2] = __expf(sacc[nt][2] - mn1);
                sacc[nt][3] = __expf(sacc[nt][3] - mn1);
                sum0 += sacc[nt][0] + sacc[nt][1];
                sum1 += sacc[nt][2] + sacc[nt][3];
            }
            sum0 += __shfl_xor_sync(0xffffffffu, sum0, 1);
            sum0 += __shfl_xor_sync(0xffffffffu, sum0, 2);
            sum1 += __shfl_xor_sync(0xffffffffu, sum1, 1);
            sum1 += __shfl_xor_sync(0xffffffffu, sum1, 2);
            l0 = l0 * sc0 + sum0;  l1 = l1 * sc1 + sum1;
            m0 = mn0;  m1 = mn1;
            #pragma unroll
            for (int nt = 0; nt < 8; nt++) {
                o[nt][0] *= sc0;  o[nt][1] *= sc0;
                o[nt][2] *= sc1;  o[nt][3] *= sc1;
            }

            // ---- O += P V  (P C-frags -> A-frags in-register, hi/lo) ----
            #pragma unroll
            for (int kt = 0; kt < 4; kt++) {
                const float* sA = sacc[2*kt];
                const float* sB = sacc[2*kt+1];
                u32 pH[4], pL[4];
                pH[0] = bf2(sA[0], sA[1]);
                pH[1] = bf2(sA[2], sA[3]);
                pH[2] = bf2(sB[0], sB[1]);
                pH[3] = bf2(sB[2], sB[3]);
                pL[0] = bf2(sA[0] - lo16f(pH[0]), sA[1] - hi16f(pH[0]));
                pL[1] = bf2(sA[2] - lo16f(pH[1]), sA[3] - hi16f(pH[1]));
                pL[2] = bf2(sB[0] - lo16f(pH[2]), sB[1] - hi16f(pH[2]));
                pL[3] = bf2(sB[2] - lo16f(pH[3]), sB[3] - hi16f(pH[3]));
                #pragma unroll
                for (int ntp = 0; ntp < 4; ntp++) {
                    int nr = ntp * 16 + browB;
                    u32 off = (u32)(nr * 128 + (((kt * 2 + bgB) ^ (nr & 7)) << 4));
                    u32 vh4[4], vl4[4];
                    ldsm4(vh4, vb + off);
                    ldsm4(vl4, vb + 8192 + off);
                    mma_bf16(o[2*ntp],   pH, vh4);
                    mma_bf16(o[2*ntp],   pH, vl4);
                    mma_bf16(o[2*ntp],   pL, vh4);
                    mma_bf16(o[2*ntp+1], pH, vh4 + 2);
                    mma_bf16(o[2*ntp+1], pH, vl4 + 2);
                    mma_bf16(o[2*ntp+1], pL, vh4 + 2);
                }
            }

            __syncthreads();
            if (tid == 0 && gi + 2 < n_iter) {
                const size_t tn = (size_t)(b * 64 + gi + 2) * 8192;
                u32 mb = s ? mb1 : mb0;
                u32 d  = smb + A_ST + s * A_STG;
                mbar_expect(mb, A_STG);
                bulk_g2s(d,         kh_g  + tn, 8192, mb);
                bulk_g2s(d + 8192,  kl_g  + tn, 8192, mb);
                bulk_g2s(d + 16384, vth_g + tn, 8192, mb);
                bulk_g2s(d + 24576, vtl_g + tn, 8192, mb);
            }
        }

        // ---- epilogue ----
        float i0 = 1.0f / l0, i1 = 1.0f / l1;
        int gr = b * TT + tq * 64 + warp * 16 + (lane >> 2);
        #pragma unroll
        for (int nt = 0; nt < 8; nt++) {
            int h = nt * 8 + 2 * (lane & 3);
            float2 w0 = make_float2(o[nt][0] * i0, o[nt][1] * i0);
            float2 w1 = make_float2(o[nt][2] * i1, o[nt][3] * i1);
            *(float2*)&out[(size_t)gr * HD + h]       = w0;
            *(float2*)&out[(size_t)(gr + 8) * HD + h] = w1;
        }
    }
}

extern "C" void kernel_launch(void* const* d_in, const int* in_sizes, int n_in,
                              void* d_out, int out_size)
{
    const float* x  = (const float*)d_in[0];
    const float* Wk = (const float*)d_in[1];
    const float* Wq = (const float*)d_in[2];
    const float* Wv = (const float*)d_in[3];
    float* out = (float*)d_out;

    cudaFuncSetAttribute(proj_kernel, cudaFuncAttributeMaxDynamicSharedMemorySize, P_SMEM);
    cudaFuncSetAttribute(attn2_kernel, cudaFuncAttributeMaxDynamicSharedMemorySize, A_SMEM);

    wconv_kernel<<<192, 256>>>(Wk, Wq, Wv);
    proj_kernel<<<BT / 128, 256, P_SMEM>>>(x);
    attn2_kernel<<<dim3(32, NB), 128, A_SMEM>>>(out);
}